// round 6
// baseline (speedup 1.0000x reference)
#include <cuda_runtime.h>
#include <cstdint>
#include <math.h>

#define B_   64
#define S_   512
#define E_   256
#define H_   512
#define O_   1000
#define NBLK 128
#define NTHR 256

// ---------------- device scratch ----------------
__device__ float g_h[2 * H_ * B_];     // [buf][j][b]
__device__ int   g_flag[NBLK * 32];    // per-CTA progress flag, 128B apart

__device__ __forceinline__ int ld_acquire_gpu(const int* p) {
    int v;
    asm volatile("ld.acquire.gpu.global.s32 %0, [%1];" : "=r"(v) : "l"(p) : "memory");
    return v;
}
__device__ __forceinline__ void st_release_gpu(int* p, int v) {
    asm volatile("st.release.gpu.global.s32 [%0], %1;" :: "l"(p), "r"(v) : "memory");
}
__device__ __forceinline__ float sigf(float v) {
    return __fdividef(1.f, 1.f + __expf(-v));
}
__device__ __forceinline__ float tanhf_fast(float v) {
    return __fdividef(2.f, 1.f + __expf(-2.f * v)) - 1.f;
}

__global__ void init_flags_kernel() { g_flag[threadIdx.x * 32] = 0; }

// ---------------- fused persistent LSTM ----------------
// 128 CTAs x 256 threads. CTA owns 4 hidden units (16 gate cols).
// warp wid: wu=wid&3 -> unit j0+wu; kh=wid>>2 -> K-half. lane -> 2 batches.
// Per step: [input phase: emb_s @ Wx (K=256, 4 chunks) — independent of peers,
// hides the flag-poll + first h load] then [recurrent: h_s @ Wh (K=512, 8 chunks)].
// Double-buffered staging (1 bar/chunk). K-halves reduced via SMEM at step end.
// Sync: identical acquire/release flag protocol as R5 (proven correct).
__global__ void __launch_bounds__(NTHR, 1) lstm_fused_kernel(
    const int* __restrict__ x,
    const float* __restrict__ hidden_in, const float* __restrict__ c_in,
    const float* __restrict__ embed_w,
    const float* __restrict__ Wf, const float* __restrict__ Wi,
    const float* __restrict__ Wc, const float* __restrict__ Wo,
    const float* __restrict__ bf, const float* __restrict__ bi,
    const float* __restrict__ bc, const float* __restrict__ bo,
    float* __restrict__ d_out)
{
    extern __shared__ float sm[];
    float* sWh = sm;            // [512][16]  32 KB
    float* sWx = sm + 8192;     // [256][16]  16 KB
    float* sB0 = sm + 12288;    // [64][64]   16 KB (staging buf 0 / reduce scratch)
    float* sB1 = sm + 16384;    // [64][64]   16 KB (staging buf 1)
    __shared__ int rows[B_];

    const int tid  = threadIdx.x;
    const int wid  = tid >> 5;
    const int lane = tid & 31;
    const int wu   = wid & 3;       // unit within CTA
    const int kh   = wid >> 2;      // K-half (0/1)
    const int j0   = blockIdx.x * 4;
    const int jme  = j0 + wu;
    const int b0   = lane * 2;
    const int eb   = tid >> 2;      // emb batch this thread stages
    const int eq   = tid & 3;       // emb quarter (16 k values)

    // ---- prologue: weights (once), biases, initial state ----
    const float* W4[4] = {Wf, Wi, Wc, Wo};
    for (int k = tid; k < E_ + H_; k += NTHR) {
        float* dst = (k < H_) ? &sWh[k * 16] : &sWx[(k - H_) * 16];
#pragma unroll
        for (int jj = 0; jj < 4; ++jj)
#pragma unroll
            for (int g = 0; g < 4; ++g)
                dst[jj * 4 + g] = W4[g][(size_t)k * H_ + j0 + jj];
    }
    const float bias0 = bf[jme], bias1 = bi[jme], bias2 = bc[jme], bias3 = bo[jme];
    const float bsc = (kh == 0) ? 1.f : 0.f;

    float c0 = 0.f, c1 = 0.f;
    if (wid < 4) {
        c0 = c_in[(b0 + 0) * H_ + jme];
        c1 = c_in[(b0 + 1) * H_ + jme];
        g_h[jme * B_ + b0 + 0] = hidden_in[(b0 + 0) * H_ + jme];
        g_h[jme * B_ + b0 + 1] = hidden_in[(b0 + 1) * H_ + jme];
    }
    if (tid < B_) rows[tid] = x[tid * S_ + 0];
    __threadfence();
    __syncthreads();
    if (tid == 0) st_release_gpu(&g_flag[blockIdx.x * 32], 1);

    for (int s = 0; s < S_; ++s) {
        const int rbuf = s & 1;
        const float* hsrc = g_h + rbuf * (H_ * B_);
        const float* erow = embed_w + (size_t)rows[eb] * E_;

        // fetch + stage emb chunk 0 (peer-independent), then flag barrier
        float4 P[4];
#pragma unroll
        for (int i = 0; i < 4; ++i)
            P[i] = *(const float4*)(erow + eq * 16 + i * 4);
#pragma unroll
        for (int i = 0; i < 4; ++i) {
            int kb = eq * 16 + i * 4;
            sB0[(kb + 0) * 64 + eb] = P[i].x; sB0[(kb + 1) * 64 + eb] = P[i].y;
            sB0[(kb + 2) * 64 + eb] = P[i].z; sB0[(kb + 3) * 64 + eb] = P[i].w;
        }
        if (tid < NBLK) {
            const int* fl = &g_flag[tid * 32];
            while (ld_acquire_gpu(fl) < s + 1) { }
        }
        __syncthreads();   // staging chunk0 done + acquire visibility CTA-wide

        float a[8];
        a[0] = bias0 * bsc; a[1] = bias1 * bsc; a[2] = bias2 * bsc; a[3] = bias3 * bsc;
        a[4] = a[0]; a[5] = a[1]; a[6] = a[2]; a[7] = a[3];

        float4 Hp[4];
        // ---- input phase: 4 emb chunks (K=256) ----
        for (int c = 0; c < 4; ++c) {
            float* bufc = (c & 1) ? sB1 : sB0;
            if (c < 3) {
#pragma unroll
                for (int i = 0; i < 4; ++i)
                    P[i] = *(const float4*)(erow + (c + 1) * 64 + eq * 16 + i * 4);
            } else {   // first h chunk (legal: after acquire barrier)
                const float4* hs4 = (const float4*)hsrc;
#pragma unroll
                for (int i = 0; i < 4; ++i) Hp[i] = __ldcg(hs4 + tid + i * NTHR);
            }
            const float* wx = sWx + (c * 64 + kh * 32) * 16 + wu * 4;
            const float* hb = bufc + (kh * 32) * 64 + b0;
#pragma unroll 32
            for (int kk = 0; kk < 32; ++kk) {
                float2 hv = *(const float2*)(hb + kk * 64);
                float4 wv = *(const float4*)(wx + kk * 16);
                a[0] += hv.x * wv.x; a[1] += hv.x * wv.y;
                a[2] += hv.x * wv.z; a[3] += hv.x * wv.w;
                a[4] += hv.y * wv.x; a[5] += hv.y * wv.y;
                a[6] += hv.y * wv.z; a[7] += hv.y * wv.w;
            }
            float* bufn = (c & 1) ? sB0 : sB1;
            if (c < 3) {
#pragma unroll
                for (int i = 0; i < 4; ++i) {
                    int kb = eq * 16 + i * 4;
                    bufn[(kb + 0) * 64 + eb] = P[i].x; bufn[(kb + 1) * 64 + eb] = P[i].y;
                    bufn[(kb + 2) * 64 + eb] = P[i].z; bufn[(kb + 3) * 64 + eb] = P[i].w;
                }
            } else {
                float4* d4 = (float4*)bufn;
#pragma unroll
                for (int i = 0; i < 4; ++i) d4[tid + i * NTHR] = Hp[i];
            }
            __syncthreads();
        }

        // ---- recurrent phase: 8 h chunks (K=512) ----
        for (int c = 0; c < 8; ++c) {
            float* bufc = (c & 1) ? sB1 : sB0;
            if (c < 7) {
                const float4* hs4 = (const float4*)(hsrc + (c + 1) * 4096);
#pragma unroll
                for (int i = 0; i < 4; ++i) Hp[i] = __ldcg(hs4 + tid + i * NTHR);
            }
            const float* wh = sWh + (c * 64 + kh * 32) * 16 + wu * 4;
            const float* hb = bufc + (kh * 32) * 64 + b0;
#pragma unroll 32
            for (int kk = 0; kk < 32; ++kk) {
                float2 hv = *(const float2*)(hb + kk * 64);
                float4 wv = *(const float4*)(wh + kk * 16);
                a[0] += hv.x * wv.x; a[1] += hv.x * wv.y;
                a[2] += hv.x * wv.z; a[3] += hv.x * wv.w;
                a[4] += hv.y * wv.x; a[5] += hv.y * wv.y;
                a[6] += hv.y * wv.z; a[7] += hv.y * wv.w;
            }
            if (c < 7) {
                float* bufn = (c & 1) ? sB0 : sB1;
                float4* d4 = (float4*)bufn;
#pragma unroll
                for (int i = 0; i < 4; ++i) d4[tid + i * NTHR] = Hp[i];
            }
            __syncthreads();
        }

        // ---- reduce K-halves (scratch = sB0, free after last bar) ----
        if (kh == 1) {
            float* scr = sB0 + (wu * 32 + lane) * 8;
#pragma unroll
            for (int i = 0; i < 8; ++i) scr[i] = a[i];
        }
        __syncthreads();
        if (kh == 0) {
            const float* scr = sB0 + (wu * 32 + lane) * 8;
#pragma unroll
            for (int i = 0; i < 8; ++i) a[i] += scr[i];

            float f0 = sigf(a[0]), i0 = sigf(a[1]);
            float g0 = tanhf_fast(a[2]), o0 = sigf(a[3]);
            c0 = f0 * c0 + i0 * g0;
            float h0 = o0 * tanhf_fast(c0);
            float f1 = sigf(a[4]), i1 = sigf(a[5]);
            float g1 = tanhf_fast(a[6]), o1 = sigf(a[7]);
            c1 = f1 * c1 + i1 * g1;
            float h1 = o1 * tanhf_fast(c1);

            if (s < S_ - 1) {
                *(float2*)&g_h[(rbuf ^ 1) * (H_ * B_) + jme * B_ + b0] = make_float2(h0, h1);
            } else {
                d_out[B_ * O_ + (b0 + 0) * H_ + jme] = h0;
                d_out[B_ * O_ + (b0 + 1) * H_ + jme] = h1;
            }
        }
        if (s < S_ - 1) {
            if (tid < B_) rows[tid] = x[tid * S_ + s + 1];
            __threadfence();
            __syncthreads();
            if (tid == 0) st_release_gpu(&g_flag[blockIdx.x * 32], s + 2);
        }
    }
}

// ---------------- dense head ----------------
__global__ void __launch_bounds__(256) dense_out_kernel(
    const float* __restrict__ Wd, const float* __restrict__ bd,
    float* __restrict__ d_out)
{
    const int o  = blockIdx.x * 256 + threadIdx.x;
    const int b0 = blockIdx.y * 2;
    __shared__ float sh[2][H_];
    const float* hsrc = d_out + B_ * O_;

    for (int idx = threadIdx.x; idx < 2 * H_; idx += 256) {
        int bi = idx >> 9;
        int j  = idx & (H_ - 1);
        sh[bi][j] = hsrc[(b0 + bi) * H_ + j];
    }
    __syncthreads();

    if (o < O_) {
        float bias = bd[o];
        float acc0 = bias, acc1 = bias;
#pragma unroll 8
        for (int j = 0; j < H_; ++j) {
            float wv = Wd[(size_t)j * O_ + o];
            acc0 += sh[0][j] * wv;
            acc1 += sh[1][j] * wv;
        }
        d_out[(b0 + 0) * O_ + o] = acc0;
        d_out[(b0 + 1) * O_ + o] = acc1;
    }
}

// ---------------- launch ----------------
extern "C" void kernel_launch(void* const* d_in, const int* in_sizes, int n_in,
                              void* d_out, int out_size) {
    const int*   x        = (const int*)  d_in[0];
    const float* hidden   = (const float*)d_in[1];
    const float* c        = (const float*)d_in[2];
    const float* embed_w  = (const float*)d_in[3];
    const float* W_f      = (const float*)d_in[4];
    const float* b_f      = (const float*)d_in[5];
    const float* W_i      = (const float*)d_in[6];
    const float* b_i      = (const float*)d_in[7];
    const float* W_c      = (const float*)d_in[8];
    const float* b_c      = (const float*)d_in[9];
    const float* W_o      = (const float*)d_in[10];
    const float* b_o      = (const float*)d_in[11];
    const float* W_d      = (const float*)d_in[12];
    const float* b_d      = (const float*)d_in[13];
    float* out = (float*)d_out;

    static bool attr_set = false;
    if (!attr_set) {
        cudaFuncSetAttribute(lstm_fused_kernel,
                             cudaFuncAttributeMaxDynamicSharedMemorySize, 81920);
        attr_set = true;
    }

    init_flags_kernel<<<1, NBLK>>>();

    lstm_fused_kernel<<<NBLK, NTHR, 81920>>>(
        x, hidden, c, embed_w, W_f, W_i, W_c, W_o,
        b_f, b_i, b_c, b_o, out);

    dim3 g3(4, 32);
    dense_out_kernel<<<g3, 256>>>(W_d, b_d, out);
}